// round 5
// baseline (speedup 1.0000x reference)
#include <cuda_runtime.h>
#include <cuda_bf16.h>
#include <cstdint>
#include <cstddef>

// ---------------------------------------------------------------------------
// Problem constants
// ---------------------------------------------------------------------------
namespace {
constexpr int Bg    = 256;
constexpr int Hc    = 128;
constexpr int NRFc  = 16;
constexpr int NUSER = 4096;    // Bg*16
constexpr int NAG   = 16384;   // Bg*64
constexpr int APAD  = 136;     // bf16 elems per smem row
constexpr int ASTR  = APAD * 2; // 272 bytes
constexpr int TILE  = 128 * ASTR;          // 34816 B per 128-row bf16 tile
// smem slot offsets (bytes)
constexpr int OF_AH  = 0;
constexpr int OF_AL  = TILE;
constexpr int OF_B1H = 2 * TILE;
constexpr int OF_B1L = 3 * TILE;
constexpr int OF_B2H = 4 * TILE;
constexpr int OF_B2L = 5 * TILE;
constexpr int SMEM_G1 = 4 * TILE;          // A + B1            (139264)
constexpr int SMEM_G2 = 6 * TILE;          // A + B1 + B2       (208896)
constexpr int NT = 512;                    // threads per block
}

// ---------------------------------------------------------------------------
// Scratch (device globals — no allocation allowed)
// ---------------------------------------------------------------------------
__device__ float g_hu   [NUSER * Hc];
__device__ float g_ha2  [NAG   * Hc];
__device__ float g_meanA [Bg * Hc];
__device__ float g_meanU [Bg * Hc];
__device__ float g_meanA2[Bg * Hc];
__device__ float g_hag  [Bg * Hc];
// Pre-transposed + hi/lo-split weights: slots 0..5 = HxH, slot 6 = W_norm' (64x128)
__device__ __nv_bfloat16 g_wt_hi[7 * Hc * Hc];
__device__ __nv_bfloat16 g_wt_lo[7 * Hc * Hc];

// ---------------------------------------------------------------------------
// Helpers
// ---------------------------------------------------------------------------
__device__ __forceinline__ uint32_t smem_u32(const void* p) {
    uint32_t a;
    asm("{ .reg .u64 t; cvta.to.shared.u64 t, %1; cvt.u32.u64 %0, t; }"
        : "=r"(a) : "l"(p));
    return a;
}
__device__ __forceinline__ void ldsm4(uint32_t* r, uint32_t addr) {
    asm volatile("ldmatrix.sync.aligned.m8n8.x4.shared.b16 {%0,%1,%2,%3}, [%4];"
                 : "=r"(r[0]), "=r"(r[1]), "=r"(r[2]), "=r"(r[3]) : "r"(addr));
}
__device__ __forceinline__ void mma16816(float* d, const uint32_t* a, const uint32_t* b) {
    asm volatile(
        "mma.sync.aligned.m16n8k16.row.col.f32.bf16.bf16.f32 "
        "{%0,%1,%2,%3}, {%4,%5,%6,%7}, {%8,%9}, {%0,%1,%2,%3};"
        : "+f"(d[0]), "+f"(d[1]), "+f"(d[2]), "+f"(d[3])
        : "r"(a[0]), "r"(a[1]), "r"(a[2]), "r"(a[3]), "r"(b[0]), "r"(b[1]));
}
__device__ __forceinline__ void cpa16(uint32_t dst, const void* src) {
    asm volatile("cp.async.cg.shared.global [%0], [%1], 16;"
                 :: "r"(dst), "l"(src) : "memory");
}
#define CP_COMMIT() asm volatile("cp.async.commit_group;" ::: "memory")
#define CP_WAIT(n)  asm volatile("cp.async.wait_group %0;" :: "n"(n) : "memory")

__device__ __forceinline__ uint32_t pack_bf2(__nv_bfloat16 a, __nv_bfloat16 b) {
    return (uint32_t)__bfloat16_as_ushort(a) | ((uint32_t)__bfloat16_as_ushort(b) << 16);
}
__device__ __forceinline__ void split2(float a, float b, uint32_t& hi, uint32_t& lo) {
    const __nv_bfloat16 h0 = __float2bfloat16(a), h1 = __float2bfloat16(b);
    hi = pack_bf2(h0, h1);
    lo = pack_bf2(__float2bfloat16(a - __bfloat162float(h0)),
                  __float2bfloat16(b - __bfloat162float(h1)));
}

// cp.async B tile (pre-split weights) into swizzle-free padded smem
__device__ __forceinline__ void load_B_async(const __nv_bfloat16* __restrict__ Wh,
                                             const __nv_bfloat16* __restrict__ Wl,
                                             uint32_t bh, uint32_t bl, int tid, int rows)
{
    const uint4* wh = reinterpret_cast<const uint4*>(Wh);
    const uint4* wl = reinterpret_cast<const uint4*>(Wl);
    for (int i = tid; i < rows * 16; i += NT) {
        const uint32_t o = (uint32_t)((i >> 4) * ASTR + (i & 15) * 16);
        cpa16(bh + o, wh + i);
        cpa16(bl + o, wl + i);
    }
}

// A tile: fp32 load (+optional group-broadcast add, group = row>>SHIFT), hi/lo split
template<int SHIFT>
__device__ __forceinline__ void load_split_A(const float* __restrict__ A,
                                             const float* __restrict__ addv,
                                             int row0, char* pAh, char* pAl, int tid)
{
    for (int i = tid; i < 128 * 16; i += NT) {
        const int r = i >> 4, k = (i & 15) * 8;
        const float* ap = A + (size_t)(row0 + r) * Hc + k;
        float v[8];
        *reinterpret_cast<float4*>(&v[0]) = *reinterpret_cast<const float4*>(ap);
        *reinterpret_cast<float4*>(&v[4]) = *reinterpret_cast<const float4*>(ap + 4);
        if (addv) {
            const float* mp = addv + ((row0 + r) >> SHIFT) * Hc + k;
            float m[8];
            *reinterpret_cast<float4*>(&m[0]) = *reinterpret_cast<const float4*>(mp);
            *reinterpret_cast<float4*>(&m[4]) = *reinterpret_cast<const float4*>(mp + 4);
            #pragma unroll
            for (int j = 0; j < 8; ++j) v[j] += m[j];
        }
        uint32_t hb[4], lb[4];
        #pragma unroll
        for (int j = 0; j < 4; ++j) split2(v[2*j], v[2*j+1], hb[j], lb[j]);
        const uint32_t o = (uint32_t)(r * ASTR + (i & 15) * 16);
        *reinterpret_cast<uint4*>(pAh + o) = *reinterpret_cast<uint4*>(hb);
        *reinterpret_cast<uint4*>(pAl + o) = *reinterpret_cast<uint4*>(lb);
    }
}

// 3-pass hi/lo MMA over K=128; warp tile 32x32 (MF=2) or 32x16 (NF=2)
template<int NF>
__device__ __forceinline__ void mma_3p(uint32_t aAh, uint32_t aAl,
                                       uint32_t aBh, uint32_t aBl,
                                       uint32_t a_off, uint32_t b_off,
                                       float (*acc)[NF][4])
{
    #pragma unroll
    for (int pass = 0; pass < 3; ++pass) {
        const uint32_t Ab = (pass == 2 ? aAl : aAh) + a_off;
        const uint32_t Bb = (pass == 1 ? aBl : aBh) + b_off;
        #pragma unroll
        for (int kc = 0; kc < 8; ++kc) {
            const uint32_t kb = (uint32_t)kc * 32;
            uint32_t af[2][4];
            #pragma unroll
            for (int mf = 0; mf < 2; ++mf)
                ldsm4(af[mf], Ab + (uint32_t)(mf * 16 * ASTR) + kb);
            uint32_t bfr[NF][2];
            #pragma unroll
            for (int p = 0; p < NF / 2; ++p) {
                uint32_t t[4];
                ldsm4(t, Bb + (uint32_t)(p * 16 * ASTR) + kb);
                bfr[2*p][0] = t[0]; bfr[2*p][1] = t[1];
                bfr[2*p+1][0] = t[2]; bfr[2*p+1][1] = t[3];
            }
            #pragma unroll
            for (int mf = 0; mf < 2; ++mf)
                #pragma unroll
                for (int nf = 0; nf < NF; ++nf)
                    mma16816(acc[mf][nf], af[mf], bfr[nf]);
        }
    }
}
__device__ __forceinline__ void zero_acc4(float (*acc)[4][4]) {
    #pragma unroll
    for (int mf = 0; mf < 2; ++mf)
        #pragma unroll
        for (int nf = 0; nf < 4; ++nf)
            acc[mf][nf][0] = acc[mf][nf][1] = acc[mf][nf][2] = acc[mf][nf][3] = 0.f;
}

// epilogue: relu(acc+b) (+mean[g]) re-split into A tiles
template<bool ADDMEAN, int SHIFT>
__device__ __forceinline__ void epi_resplit(float (*acc)[4][4],
                                            const float* __restrict__ bias,
                                            const float* __restrict__ meanv,
                                            char* pAh, char* pAl,
                                            int row0, int m0, int n0, int lane)
{
    const int tq = lane & 3, gq = lane >> 2;
    #pragma unroll
    for (int mf = 0; mf < 2; ++mf) {
        const int r0 = m0 + mf * 16 + gq;
        const int g = ADDMEAN ? ((SHIFT == 6) ? ((row0 + m0) >> 6)
                                              : ((row0 + m0 + mf * 16) >> 4)) : 0;
        #pragma unroll
        for (int nf = 0; nf < 4; ++nf) {
            const int c = n0 + nf * 8 + 2 * tq;
            float mx = 0.f, my = 0.f;
            if (ADDMEAN) {
                const float2 mv = *reinterpret_cast<const float2*>(&meanv[g * Hc + c]);
                mx = mv.x; my = mv.y;
            }
            const float bb0 = bias[c], bb1 = bias[c + 1];
            const float e0 = fmaxf(acc[mf][nf][0] + bb0, 0.f) + mx;
            const float e1 = fmaxf(acc[mf][nf][1] + bb1, 0.f) + my;
            const float e2 = fmaxf(acc[mf][nf][2] + bb0, 0.f) + mx;
            const float e3 = fmaxf(acc[mf][nf][3] + bb1, 0.f) + my;
            uint32_t hi0, lo0, hi1, lo1;
            split2(e0, e1, hi0, lo0);
            split2(e2, e3, hi1, lo1);
            *reinterpret_cast<uint32_t*>(pAh + r0 * ASTR + c * 2) = hi0;
            *reinterpret_cast<uint32_t*>(pAl + r0 * ASTR + c * 2) = lo0;
            *reinterpret_cast<uint32_t*>(pAh + (r0 + 8) * ASTR + c * 2) = hi1;
            *reinterpret_cast<uint32_t*>(pAl + (r0 + 8) * ASTR + c * 2) = lo1;
        }
    }
}

// mean-16 epilogue: per mf frag (16 rows = 1 group)
__device__ __forceinline__ void epi_mean16(float (*acc)[4][4],
                                           const float* __restrict__ bias,
                                           float* __restrict__ outp,
                                           int row0, int m0, int n0, int lane)
{
    const int tq = lane & 3;
    #pragma unroll
    for (int mf = 0; mf < 2; ++mf) {
        const int grp = (row0 + m0 + mf * 16) >> 4;
        #pragma unroll
        for (int nf = 0; nf < 4; ++nf) {
            const int c = n0 + nf * 8 + 2 * tq;
            const float bb0 = bias[c], bb1 = bias[c + 1];
            float s0 = fmaxf(acc[mf][nf][0] + bb0, 0.f)
                     + fmaxf(acc[mf][nf][2] + bb0, 0.f);
            float s1 = fmaxf(acc[mf][nf][1] + bb1, 0.f)
                     + fmaxf(acc[mf][nf][3] + bb1, 0.f);
            s0 += __shfl_xor_sync(~0u, s0, 4);  s1 += __shfl_xor_sync(~0u, s1, 4);
            s0 += __shfl_xor_sync(~0u, s0, 8);  s1 += __shfl_xor_sync(~0u, s1, 8);
            s0 += __shfl_xor_sync(~0u, s0, 16); s1 += __shfl_xor_sync(~0u, s1, 16);
            if (lane < 4) {
                float2 o2 = {s0 * 0.0625f, s1 * 0.0625f};
                *reinterpret_cast<float2*>(&outp[grp * Hc + n0 + nf * 8 + 2 * lane]) = o2;
            }
        }
    }
}

// ---------------------------------------------------------------------------
// K1: prep (blocks 0..6) + stage1 (blocks 7..38)
// ---------------------------------------------------------------------------
__global__ __launch_bounds__(NT, 1)
void k1_prep_stage1(const float* W0, const float* W1, const float* W2,
                    const float* W3, const float* W4, const float* W5,
                    const float* Wn,
                    __nv_bfloat16* oh, __nv_bfloat16* ol,
                    const float* __restrict__ uf,
                    const float* __restrict__ W_ue, const float* __restrict__ b_ue,
                    const float* __restrict__ W_t,  const float* __restrict__ b_t,
                    float* __restrict__ hu, float* __restrict__ hag)
{
    extern __shared__ char smraw[];
    const int tid = threadIdx.x;

    if (blockIdx.x < 7) {
        float* st = reinterpret_cast<float*>(smraw);
        const int m = blockIdx.x;
        uint32_t* ph = reinterpret_cast<uint32_t*>(oh + (size_t)m * Hc * Hc);
        uint32_t* pl = reinterpret_cast<uint32_t*>(ol + (size_t)m * Hc * Hc);
        if (m < 6) {
            const float* Ws[6] = {W0, W1, W2, W3, W4, W5};
            const float* W = Ws[m];
            for (int i = tid; i < Hc * 32; i += NT) {
                const int kr = i >> 5, c4 = i & 31;
                *reinterpret_cast<float4*>(&st[kr * 132 + c4 * 4]) =
                    reinterpret_cast<const float4*>(W)[i];
            }
            __syncthreads();
            for (int i = tid; i < Hc * 64; i += NT) {
                const int n = i >> 6, k2 = (i & 63) * 2;
                uint32_t hi, lo;
                split2(st[k2 * 132 + n], st[(k2 + 1) * 132 + n], hi, lo);
                ph[n * 64 + (i & 63)] = hi;
                pl[n * 64 + (i & 63)] = lo;
            }
        } else {
            for (int i = tid; i < Hc * 8; i += NT) {
                const int kr = i >> 3, c4 = i & 7;
                *reinterpret_cast<float4*>(&st[kr * 36 + c4 * 4]) =
                    reinterpret_cast<const float4*>(Wn)[i];
            }
            __syncthreads();
            for (int i = tid; i < 64 * 64; i += NT) {
                const int rowp = i >> 6, k = (i & 63) * 2;
                uint32_t hi = 0, lo = 0;
                if (rowp < 32) {
                    const int n = (rowp & 1) * 16 + (rowp >> 1);
                    split2(st[k * 36 + n], st[(k + 1) * 36 + n], hi, lo);
                }
                ph[rowp * 64 + (i & 63)] = hi;
                pl[rowp * 64 + (i & 63)] = lo;
            }
        }
        return;
    }

    // ---- stage1 ----
    float* sA    = reinterpret_cast<float*>(smraw);           // [128][36]
    float* sW    = reinterpret_cast<float*>(smraw + 18432);   // [32][128]
    float* spart = reinterpret_cast<float*>(smraw + 65536);   // [16][132]
    float* smean = reinterpret_cast<float*>(smraw + 73984);   // [8][132]
    float* sWt   = reinterpret_cast<float*>(smraw);           // phase2: [128][128]

    const int row0 = (blockIdx.x - 7) * 128;

    for (int i = tid; i < 1024; i += NT) {
        const int r = i >> 3, k4 = i & 7;
        *reinterpret_cast<float4*>(&sA[r * 36 + k4 * 4]) =
            reinterpret_cast<const float4*>(uf)[(size_t)row0 * 8 + i];
    }
    for (int i = tid; i < 1024; i += NT)
        reinterpret_cast<float4*>(sW)[i] = reinterpret_cast<const float4*>(W_ue)[i];
    __syncthreads();

    {
        const int tx = tid & 31, ty = tid >> 5;    // ty 0..15, 8 rows each
        const float4 b4 = reinterpret_cast<const float4*>(b_ue)[tx];
        float4 msum = {0.f, 0.f, 0.f, 0.f};
        #pragma unroll 2
        for (int i = 0; i < 8; ++i) {
            const int r = ty * 8 + i;
            float4 acc = b4;
            #pragma unroll
            for (int k = 0; k < 32; ++k) {
                const float a = sA[r * 36 + k];
                const float4 w = reinterpret_cast<const float4*>(sW)[k * 32 + tx];
                acc.x += a * w.x; acc.y += a * w.y; acc.z += a * w.z; acc.w += a * w.w;
            }
            acc.x = fmaxf(acc.x, 0.f); acc.y = fmaxf(acc.y, 0.f);
            acc.z = fmaxf(acc.z, 0.f); acc.w = fmaxf(acc.w, 0.f);
            reinterpret_cast<float4*>(hu)[(size_t)(row0 + r) * 32 + tx] = acc;
            msum.x += acc.x; msum.y += acc.y; msum.z += acc.z; msum.w += acc.w;
        }
        *reinterpret_cast<float4*>(&spart[ty * 132 + tx * 4]) = msum;
    }
    __syncthreads();
    for (int i = tid; i < 1024; i += NT) {
        const int g = i >> 7, c = i & 127;
        smean[g * 132 + c] = (spart[(2*g) * 132 + c] + spart[(2*g+1) * 132 + c]) * 0.0625f;
    }
    __syncthreads();
    for (int i = tid; i < 4096; i += NT)
        reinterpret_cast<float4*>(sWt)[i] = reinterpret_cast<const float4*>(W_t)[i];
    __syncthreads();
    if (tid < 256) {
        const int gr = tid >> 5, col4 = tid & 31;
        float4 acc = reinterpret_cast<const float4*>(b_t)[col4];
        #pragma unroll 4
        for (int k = 0; k < 128; ++k) {
            const float a = smean[gr * 132 + k];
            const float4 w = reinterpret_cast<const float4*>(sWt)[k * 32 + col4];
            acc.x += a * w.x; acc.y += a * w.y; acc.z += a * w.z; acc.w += a * w.w;
        }
        acc.x = fmaxf(acc.x, 0.f); acc.y = fmaxf(acc.y, 0.f);
        acc.z = fmaxf(acc.z, 0.f); acc.w = fmaxf(acc.w, 0.f);
        reinterpret_cast<float4*>(hag)[(size_t)((blockIdx.x - 7) * 8 + gr) * 32 + col4] = acc;
    }
}

// ---------------------------------------------------------------------------
// K2: conv1 aggr GEMMs.  blocks [0,32): meanA = mean16(relu(hu@W0+b));
//                        blocks [32,160): meanU = mean64(relu((noise+hag)@W3+b))
// ---------------------------------------------------------------------------
__global__ __launch_bounds__(NT, 1)
void k2_aggr(const float* __restrict__ hu,
             const float* __restrict__ noise, const float* __restrict__ hag,
             const __nv_bfloat16* __restrict__ WH0, const __nv_bfloat16* __restrict__ WL0,
             const float* __restrict__ b_aggr_a,
             const __nv_bfloat16* __restrict__ WH3, const __nv_bfloat16* __restrict__ WL3,
             const float* __restrict__ b_aggr_u,
             float* __restrict__ meanA, float* __restrict__ meanU)
{
    extern __shared__ char sm[];
    __shared__ float spart[16][32];
    const int tid = threadIdx.x;
    const bool pa = blockIdx.x < 32;
    const int row0 = (pa ? blockIdx.x : (blockIdx.x - 32)) * 128;

    const uint32_t base = smem_u32(sm);
    load_B_async(pa ? WH0 : WH3, pa ? WL0 : WL3, base + OF_B1H, base + OF_B1L, tid, 128);
    CP_COMMIT();
    load_split_A<6>(pa ? hu : noise, pa ? nullptr : hag, row0, sm + OF_AH, sm + OF_AL, tid);
    CP_WAIT(0);
    __syncthreads();

    const int w = tid >> 5, lane = tid & 31;
    const int m0 = (w >> 2) * 32, n0 = (w & 3) * 32;
    const int rr = lane & 7, quad = lane >> 3;
    const uint32_t a_off = (uint32_t)((m0 + rr + ((quad & 1) << 3)) * ASTR + ((quad & 2) << 3));
    const uint32_t b_off = (uint32_t)((n0 + rr + ((quad >> 1) << 3)) * ASTR + ((quad & 1) << 4));

    float acc[2][4][4];
    zero_acc4(acc);
    mma_3p<4>(base + OF_AH, base + OF_AL, base + OF_B1H, base + OF_B1L, a_off, b_off, acc);

    const float* bias = pa ? b_aggr_a : b_aggr_u;
    if (pa) {
        epi_mean16(acc, bias, meanA, row0, m0, n0, lane);
    } else {
        const int tq = lane & 3;
        float s0[4], s1[4];
        #pragma unroll
        for (int nf = 0; nf < 4; ++nf) {
            const int c = n0 + nf * 8 + 2 * tq;
            const float bb0 = bias[c], bb1 = bias[c + 1];
            s0[nf] = fmaxf(acc[0][nf][0] + bb0, 0.f) + fmaxf(acc[0][nf][2] + bb0, 0.f)
                   + fmaxf(acc[1][nf][0] + bb0, 0.f) + fmaxf(acc[1][nf][2] + bb0, 0.f);
            s1[nf] = fmaxf(acc[0][nf][1] + bb1, 0.f) + fmaxf(acc[0][nf][3] + bb1, 0.f)
                   + fmaxf(acc[1][nf][1] + bb1, 0.f) + fmaxf(acc[1][nf][3] + bb1, 0.f);
            s0[nf] += __shfl_xor_sync(~0u, s0[nf], 4);  s1[nf] += __shfl_xor_sync(~0u, s1[nf], 4);
            s0[nf] += __shfl_xor_sync(~0u, s0[nf], 8);  s1[nf] += __shfl_xor_sync(~0u, s1[nf], 8);
            s0[nf] += __shfl_xor_sync(~0u, s0[nf], 16); s1[nf] += __shfl_xor_sync(~0u, s1[nf], 16);
            if (lane < 4) {
                spart[w][nf * 8 + 2 * lane]     = s0[nf];
                spart[w][nf * 8 + 2 * lane + 1] = s1[nf];
            }
        }
        __syncthreads();
        if (tid < 256) {
            const int g = tid >> 7, c = tid & 127;
            const int wn = c >> 5, ci = c & 31;
            const float s = spart[8 * g + wn][ci] + spart[8 * g + 4 + wn][ci];
            meanU[((row0 >> 6) + g) * Hc + c] = s * (1.0f / 64.0f);
        }
    }
}

// ---------------------------------------------------------------------------
// K3: blocks [0,128): agent dual  ha2 = relu((relu((noise+hag)@W1+b1)+meanA)@W2+b2)
//     blocks [128,160): user triple  meanA2 = mean16(relu(
//         relu((relu(hu@W4+b4)+meanU)@W5+b5) @ W0 + b0))
// ---------------------------------------------------------------------------
__global__ __launch_bounds__(NT, 1)
void k3_mid(const float* __restrict__ noise, const float* __restrict__ hag,
            const float* __restrict__ hu,
            const __nv_bfloat16* WH1, const __nv_bfloat16* WL1, const float* b_self_a,
            const __nv_bfloat16* WH2, const __nv_bfloat16* WL2, const float* b_comb_a,
            const float* __restrict__ meanA, float* __restrict__ ha2,
            const __nv_bfloat16* WH4, const __nv_bfloat16* WL4, const float* b_self_u,
            const __nv_bfloat16* WH5, const __nv_bfloat16* WL5, const float* b_comb_u,
            const float* __restrict__ meanU,
            const __nv_bfloat16* WH0, const __nv_bfloat16* WL0, const float* b_aggr_a,
            float* __restrict__ meanA2)
{
    extern __shared__ char sm[];
    const int tid = threadIdx.x;
    const bool agent = blockIdx.x < 128;
    const int row0 = (agent ? blockIdx.x : (blockIdx.x - 128)) * 128;

    const uint32_t base = smem_u32(sm);
    load_B_async(agent ? WH1 : WH4, agent ? WL1 : WL4, base + OF_B1H, base + OF_B1L, tid, 128);
    CP_COMMIT();                                              // G0
    load_split_A<6>(agent ? noise : hu, agent ? hag : nullptr, row0,
                    sm + OF_AH, sm + OF_AL, tid);
    load_B_async(agent ? WH2 : WH5, agent ? WL2 : WL5, base + OF_B2H, base + OF_B2L, tid, 128);
    CP_COMMIT();                                              // G1
    CP_WAIT(1);                                               // B1 ready
    __syncthreads();

    const int w = tid >> 5, lane = tid & 31;
    const int m0 = (w >> 2) * 32, n0 = (w & 3) * 32;
    const int rr = lane & 7, quad = lane >> 3;
    const uint32_t a_off = (uint32_t)((m0 + rr + ((quad & 1) << 3)) * ASTR + ((quad & 2) << 3));
    const uint32_t b_off = (uint32_t)((n0 + rr + ((quad >> 1) << 3)) * ASTR + ((quad & 1) << 4));

    float acc[2][4][4];
    zero_acc4(acc);
    mma_3p<4>(base + OF_AH, base + OF_AL, base + OF_B1H, base + OF_B1L, a_off, b_off, acc);
    __syncthreads();

    if (agent) {
        epi_resplit<true, 6>(acc, b_self_a, meanA, sm + OF_AH, sm + OF_AL,
                             row0, m0, n0, lane);
        CP_WAIT(0);                                           // B2 ready
        __syncthreads();
        zero_acc4(acc);
        mma_3p<4>(base + OF_AH, base + OF_AL, base + OF_B2H, base + OF_B2L,
                  a_off, b_off, acc);
        // store ha2 = relu(acc + b_comb_a)
        const int tq = lane & 3, gq = lane >> 2;
        #pragma unroll
        for (int mf = 0; mf < 2; ++mf) {
            const int row = row0 + m0 + mf * 16 + gq;
            #pragma unroll
            for (int nf = 0; nf < 4; ++nf) {
                const int c = n0 + nf * 8 + 2 * tq;
                const float bb0 = b_comb_a[c], bb1 = b_comb_a[c + 1];
                float2 lo = {fmaxf(acc[mf][nf][0] + bb0, 0.f),
                             fmaxf(acc[mf][nf][1] + bb1, 0.f)};
                float2 hi = {fmaxf(acc[mf][nf][2] + bb0, 0.f),
                             fmaxf(acc[mf][nf][3] + bb1, 0.f)};
                *reinterpret_cast<float2*>(&ha2[(size_t)row * Hc + c]) = lo;
                *reinterpret_cast<float2*>(&ha2[(size_t)(row + 8) * Hc + c]) = hi;
            }
        }
    } else {
        epi_resplit<true, 4>(acc, b_self_u, meanU, sm + OF_AH, sm + OF_AL,
                             row0, m0, n0, lane);
        load_B_async(WH0, WL0, base + OF_B1H, base + OF_B1L, tid, 128);  // B3 into B1 slot
        CP_COMMIT();                                          // G2
        CP_WAIT(1);                                           // B2 ready
        __syncthreads();
        zero_acc4(acc);
        mma_3p<4>(base + OF_AH, base + OF_AL, base + OF_B2H, base + OF_B2L,
                  a_off, b_off, acc);
        __syncthreads();
        epi_resplit<false, 0>(acc, b_comb_u, nullptr, sm + OF_AH, sm + OF_AL,
                              row0, m0, n0, lane);
        CP_WAIT(0);                                           // B3 ready
        __syncthreads();
        zero_acc4(acc);
        mma_3p<4>(base + OF_AH, base + OF_AL, base + OF_B1H, base + OF_B1L,
                  a_off, b_off, acc);
        epi_mean16(acc, b_aggr_a, meanA2, row0, m0, n0, lane);
    }
}

// ---------------------------------------------------------------------------
// K4: final triple.  out = normalize( relu((relu(ha2@W1+b1)+meanA2)@W2+b2) @ W_norm' + b_norm )
// ---------------------------------------------------------------------------
__global__ __launch_bounds__(NT, 1)
void k4_final(const float* __restrict__ ha2,
              const __nv_bfloat16* WH1, const __nv_bfloat16* WL1, const float* b_self_a,
              const __nv_bfloat16* WH2, const __nv_bfloat16* WL2, const float* b_comb_a,
              const float* __restrict__ meanA2,
              const __nv_bfloat16* WH6, const __nv_bfloat16* WL6, const float* b_norm,
              float* __restrict__ outp)
{
    extern __shared__ char sm[];
    const int tid = threadIdx.x;
    const int row0 = blockIdx.x * 128;

    const uint32_t base = smem_u32(sm);
    load_B_async(WH1, WL1, base + OF_B1H, base + OF_B1L, tid, 128);
    CP_COMMIT();                                              // G0
    load_split_A<6>(ha2, nullptr, row0, sm + OF_AH, sm + OF_AL, tid);
    load_B_async(WH2, WL2, base + OF_B2H, base + OF_B2L, tid, 128);
    CP_COMMIT();                                              // G1
    CP_WAIT(1);
    __syncthreads();

    const int w = tid >> 5, lane = tid & 31;
    const int m0 = (w >> 2) * 32, n0 = (w & 3) * 32;
    const int rr = lane & 7, quad = lane >> 3;
    const uint32_t a_off = (uint32_t)((m0 + rr + ((quad & 1) << 3)) * ASTR + ((quad & 2) << 3));
    const uint32_t b_off = (uint32_t)((n0 + rr + ((quad >> 1) << 3)) * ASTR + ((quad & 1) << 4));

    float acc[2][4][4];
    zero_acc4(acc);
    mma_3p<4>(base + OF_AH, base + OF_AL, base + OF_B1H, base + OF_B1L, a_off, b_off, acc);
    __syncthreads();
    epi_resplit<true, 6>(acc, b_self_a, meanA2, sm + OF_AH, sm + OF_AL, row0, m0, n0, lane);
    load_B_async(WH6, WL6, base + OF_B1H, base + OF_B1L, tid, 64);   // W_norm' into B1
    CP_COMMIT();                                              // G2
    CP_WAIT(1);                                               // B2 ready
    __syncthreads();
    zero_acc4(acc);
    mma_3p<4>(base + OF_AH, base + OF_AL, base + OF_B2H, base + OF_B2L, a_off, b_off, acc);
    __syncthreads();
    epi_resplit<false, 0>(acc, b_comb_a, nullptr, sm + OF_AH, sm + OF_AL, row0, m0, n0, lane);
    CP_WAIT(0);                                               // W_norm' ready
    __syncthreads();

    const int n03 = (w & 3) * 16;
    const uint32_t b_off3 = (uint32_t)((n03 + rr + ((quad >> 1) << 3)) * ASTR + ((quad & 1) << 4));
    float acc3[2][2][4];
    #pragma unroll
    for (int mf = 0; mf < 2; ++mf)
        #pragma unroll
        for (int nf = 0; nf < 2; ++nf)
            acc3[mf][nf][0] = acc3[mf][nf][1] = acc3[mf][nf][2] = acc3[mf][nf][3] = 0.f;
    mma_3p<2>(base + OF_AH, base + OF_AL, base + OF_B1H, base + OF_B1L, a_off, b_off3, acc3);

    if ((w & 3) < 2) {
        const int tq = lane & 3, gq = lane >> 2;
        #pragma unroll
        for (int mf = 0; mf < 2; ++mf) {
            const int row = row0 + m0 + mf * 16 + gq;
            #pragma unroll
            for (int nf = 0; nf < 2; ++nf) {
                const int c = n03 + nf * 8 + 2 * tq;   // even col; rf = c/2
                const int rf = c >> 1;
                const float br = b_norm[rf], bi = b_norm[rf + NRFc];
                {
                    const float re = acc3[mf][nf][0] + br;
                    const float im = acc3[mf][nf][1] + bi;
                    const float inv = rsqrtf(re * re + im * im);
                    float2 o = {re * inv, im * inv};
                    *reinterpret_cast<float2*>(&outp[(size_t)row * 32 + c]) = o;
                }
                {
                    const float re = acc3[mf][nf][2] + br;
                    const float im = acc3[mf][nf][3] + bi;
                    const float inv = rsqrtf(re * re + im * im);
                    float2 o = {re * inv, im * inv};
                    *reinterpret_cast<float2*>(&outp[(size_t)(row + 8) * 32 + c]) = o;
                }
            }
        }
    }
}

// ---------------------------------------------------------------------------
// Host
// ---------------------------------------------------------------------------
extern "C" void kernel_launch(void* const* d_in, const int* in_sizes, int n_in,
                              void* d_out, int out_size)
{
    (void)in_sizes; (void)n_in; (void)out_size;

    const float* user_feat = (const float*)d_in[0];
    const float* noise     = (const float*)d_in[1];
    const float* W_ue     = (const float*)d_in[6],  *b_ue     = (const float*)d_in[7];
    const float* W_t      = (const float*)d_in[8],  *b_t      = (const float*)d_in[9];
    const float* b_aggr_a = (const float*)d_in[11];
    const float* b_self_a = (const float*)d_in[13];
    const float* b_comb_a = (const float*)d_in[15];
    const float* b_aggr_u = (const float*)d_in[17];
    const float* b_self_u = (const float*)d_in[19];
    const float* b_comb_u = (const float*)d_in[21];
    const float* W_norm   = (const float*)d_in[22], *b_norm   = (const float*)d_in[23];
    float* out = (float*)d_out;

    float *hu, *ha2, *meanA, *meanU, *meanA2, *hag;
    __nv_bfloat16 *wth, *wtl;
    cudaGetSymbolAddress((void**)&hu,     g_hu);
    cudaGetSymbolAddress((void**)&ha2,    g_ha2);
    cudaGetSymbolAddress((void**)&meanA,  g_meanA);
    cudaGetSymbolAddress((void**)&meanU,  g_meanU);
    cudaGetSymbolAddress((void**)&meanA2, g_meanA2);
    cudaGetSymbolAddress((void**)&hag,    g_hag);
    cudaGetSymbolAddress((void**)&wth,    g_wt_hi);
    cudaGetSymbolAddress((void**)&wtl,    g_wt_lo);

    constexpr int SM_K1 = 78208;

    cudaFuncSetAttribute((void*)k1_prep_stage1, cudaFuncAttributeMaxDynamicSharedMemorySize, SM_K1);
    cudaFuncSetAttribute((void*)k2_aggr,  cudaFuncAttributeMaxDynamicSharedMemorySize, SMEM_G1);
    cudaFuncSetAttribute((void*)k3_mid,   cudaFuncAttributeMaxDynamicSharedMemorySize, SMEM_G2);
    cudaFuncSetAttribute((void*)k4_final, cudaFuncAttributeMaxDynamicSharedMemorySize, SMEM_G2);

    const __nv_bfloat16 *WH0 = wth + 0*16384, *WL0 = wtl + 0*16384;   // aggr_a
    const __nv_bfloat16 *WH1 = wth + 1*16384, *WL1 = wtl + 1*16384;   // self_a
    const __nv_bfloat16 *WH2 = wth + 2*16384, *WL2 = wtl + 2*16384;   // comb_a
    const __nv_bfloat16 *WH3 = wth + 3*16384, *WL3 = wtl + 3*16384;   // aggr_u
    const __nv_bfloat16 *WH4 = wth + 4*16384, *WL4 = wtl + 4*16384;   // self_u
    const __nv_bfloat16 *WH5 = wth + 5*16384, *WL5 = wtl + 5*16384;   // comb_u
    const __nv_bfloat16 *WH6 = wth + 6*16384, *WL6 = wtl + 6*16384;   // W_norm'

    k1_prep_stage1<<<7 + NUSER/128, NT, SM_K1>>>(
        (const float*)d_in[10], (const float*)d_in[12], (const float*)d_in[14],
        (const float*)d_in[16], (const float*)d_in[18], (const float*)d_in[20],
        W_norm, wth, wtl,
        user_feat, W_ue, b_ue, W_t, b_t, hu, hag);

    k2_aggr<<<32 + NAG/128, NT, SMEM_G1>>>(
        hu, noise, hag, WH0, WL0, b_aggr_a, WH3, WL3, b_aggr_u, meanA, meanU);

    k3_mid<<<128 + NUSER/128, NT, SMEM_G2>>>(
        noise, hag, hu,
        WH1, WL1, b_self_a, WH2, WL2, b_comb_a, meanA, ha2,
        WH4, WL4, b_self_u, WH5, WL5, b_comb_u, meanU,
        WH0, WL0, b_aggr_a, meanA2);

    k4_final<<<NAG/128, NT, SMEM_G2>>>(
        ha2, WH1, WL1, b_self_a, WH2, WL2, b_comb_a, meanA2,
        WH6, WL6, b_norm, out);
}

// round 6
// speedup vs baseline: 1.2647x; 1.2647x over previous
#include <cuda_runtime.h>
#include <cuda_bf16.h>
#include <cstdint>
#include <cstddef>

// ---------------------------------------------------------------------------
// Problem constants
// ---------------------------------------------------------------------------
namespace {
constexpr int Bg    = 256;
constexpr int Hc    = 128;
constexpr int NRFc  = 16;
constexpr int NUSER = 4096;    // Bg*16
constexpr int NAG   = 16384;   // Bg*64
constexpr int APAD  = 136;     // bf16 elems per smem row
constexpr int ASTR  = APAD * 2; // 272 bytes
constexpr int T64   = 64  * ASTR;   // 17408
constexpr int T128  = 128 * ASTR;   // 34816
constexpr int NT    = 256;          // threads for GEMM kernels
constexpr int NTK1  = 512;          // threads for k1
}

// ---------------------------------------------------------------------------
// Scratch (device globals — no allocation allowed)
// ---------------------------------------------------------------------------
__device__ float g_hu    [NUSER * Hc];
__device__ float g_ha2   [NAG   * Hc];
__device__ float g_meanA [Bg * Hc];
__device__ float g_meanU [Bg * Hc];
__device__ float g_meanA2[Bg * Hc];
__device__ float g_hag   [Bg * Hc];
// Pre-transposed + hi/lo-split weights: slots 0..5 = HxH, slot 6 = W_norm' (64x128)
__device__ __nv_bfloat16 g_wt_hi[7 * Hc * Hc];
__device__ __nv_bfloat16 g_wt_lo[7 * Hc * Hc];

// ---------------------------------------------------------------------------
// Helpers
// ---------------------------------------------------------------------------
__device__ __forceinline__ uint32_t smem_u32(const void* p) {
    uint32_t a;
    asm("{ .reg .u64 t; cvta.to.shared.u64 t, %1; cvt.u32.u64 %0, t; }"
        : "=r"(a) : "l"(p));
    return a;
}
__device__ __forceinline__ void ldsm4(uint32_t* r, uint32_t addr) {
    asm volatile("ldmatrix.sync.aligned.m8n8.x4.shared.b16 {%0,%1,%2,%3}, [%4];"
                 : "=r"(r[0]), "=r"(r[1]), "=r"(r[2]), "=r"(r[3]) : "r"(addr));
}
__device__ __forceinline__ void mma16816(float* d, const uint32_t* a, const uint32_t* b) {
    asm volatile(
        "mma.sync.aligned.m16n8k16.row.col.f32.bf16.bf16.f32 "
        "{%0,%1,%2,%3}, {%4,%5,%6,%7}, {%8,%9}, {%0,%1,%2,%3};"
        : "+f"(d[0]), "+f"(d[1]), "+f"(d[2]), "+f"(d[3])
        : "r"(a[0]), "r"(a[1]), "r"(a[2]), "r"(a[3]), "r"(b[0]), "r"(b[1]));
}
__device__ __forceinline__ void cpa16(uint32_t dst, const void* src) {
    asm volatile("cp.async.cg.shared.global [%0], [%1], 16;"
                 :: "r"(dst), "l"(src) : "memory");
}
#define CP_COMMIT() asm volatile("cp.async.commit_group;" ::: "memory")
#define CP_WAIT(n)  asm volatile("cp.async.wait_group %0;" :: "n"(n) : "memory")

__device__ __forceinline__ uint32_t pack_bf2(__nv_bfloat16 a, __nv_bfloat16 b) {
    return (uint32_t)__bfloat16_as_ushort(a) | ((uint32_t)__bfloat16_as_ushort(b) << 16);
}
__device__ __forceinline__ void split2(float a, float b, uint32_t& hi, uint32_t& lo) {
    const __nv_bfloat16 h0 = __float2bfloat16(a), h1 = __float2bfloat16(b);
    hi = pack_bf2(h0, h1);
    lo = pack_bf2(__float2bfloat16(a - __bfloat162float(h0)),
                  __float2bfloat16(b - __bfloat162float(h1)));
}

// cp.async B tile (pre-split weights) into padded smem
__device__ __forceinline__ void load_B_async(const __nv_bfloat16* __restrict__ Wh,
                                             const __nv_bfloat16* __restrict__ Wl,
                                             uint32_t bh, uint32_t bl, int tid, int rows)
{
    const uint4* wh = reinterpret_cast<const uint4*>(Wh);
    const uint4* wl = reinterpret_cast<const uint4*>(Wl);
    for (int i = tid; i < rows * 16; i += NT) {
        const uint32_t o = (uint32_t)((i >> 4) * ASTR + (i & 15) * 16);
        cpa16(bh + o, wh + i);
        cpa16(bl + o, wl + i);
    }
}

// A tile: fp32 load (+optional group-broadcast add), hi/lo split to smem
template<int TM, int SHIFT>
__device__ __forceinline__ void load_split_A(const float* __restrict__ A,
                                             const float* __restrict__ addv,
                                             int row0, char* pAh, char* pAl, int tid)
{
    for (int i = tid; i < TM * 16; i += NT) {
        const int r = i >> 4, k = (i & 15) * 8;
        const float* ap = A + (size_t)(row0 + r) * Hc + k;
        float v[8];
        *reinterpret_cast<float4*>(&v[0]) = *reinterpret_cast<const float4*>(ap);
        *reinterpret_cast<float4*>(&v[4]) = *reinterpret_cast<const float4*>(ap + 4);
        if (addv) {
            const float* mp = addv + ((row0 + r) >> SHIFT) * Hc + k;
            float m[8];
            *reinterpret_cast<float4*>(&m[0]) = *reinterpret_cast<const float4*>(mp);
            *reinterpret_cast<float4*>(&m[4]) = *reinterpret_cast<const float4*>(mp + 4);
            #pragma unroll
            for (int j = 0; j < 8; ++j) v[j] += m[j];
        }
        uint32_t hb[4], lb[4];
        #pragma unroll
        for (int j = 0; j < 4; ++j) split2(v[2*j], v[2*j+1], hb[j], lb[j]);
        const uint32_t o = (uint32_t)(r * ASTR + (i & 15) * 16);
        *reinterpret_cast<uint4*>(pAh + o) = *reinterpret_cast<uint4*>(hb);
        *reinterpret_cast<uint4*>(pAl + o) = *reinterpret_cast<uint4*>(lb);
    }
}

// Merged 3-product MMA over K=128: per k-chunk load Ah/Al/Bh/Bl once,
// issue Ah*Bh + Ah*Bl + Al*Bh.  (Same math as 3-pass, 33% fewer ldsm.)
template<int MF, int NF>
__device__ __forceinline__ void mma_merged(uint32_t aAh, uint32_t aAl,
                                           uint32_t aBh, uint32_t aBl,
                                           uint32_t a_off, uint32_t b_off,
                                           float (*acc)[NF][4])
{
    const uint32_t Ah = aAh + a_off, Al = aAl + a_off;
    const uint32_t Bh = aBh + b_off, Bl = aBl + b_off;
    #pragma unroll
    for (int kc = 0; kc < 8; ++kc) {
        const uint32_t kb = (uint32_t)kc * 32;
        uint32_t ah[MF][4], al[MF][4];
        #pragma unroll
        for (int mf = 0; mf < MF; ++mf) {
            ldsm4(ah[mf], Ah + (uint32_t)(mf * 16 * ASTR) + kb);
            ldsm4(al[mf], Al + (uint32_t)(mf * 16 * ASTR) + kb);
        }
        uint32_t bh[NF][2], bl[NF][2];
        #pragma unroll
        for (int p = 0; p < NF / 2; ++p) {
            uint32_t t[4];
            ldsm4(t, Bh + (uint32_t)(p * 16 * ASTR) + kb);
            bh[2*p][0] = t[0]; bh[2*p][1] = t[1];
            bh[2*p+1][0] = t[2]; bh[2*p+1][1] = t[3];
            ldsm4(t, Bl + (uint32_t)(p * 16 * ASTR) + kb);
            bl[2*p][0] = t[0]; bl[2*p][1] = t[1];
            bl[2*p+1][0] = t[2]; bl[2*p+1][1] = t[3];
        }
        #pragma unroll
        for (int mf = 0; mf < MF; ++mf)
            #pragma unroll
            for (int nf = 0; nf < NF; ++nf) {
                mma16816(acc[mf][nf], ah[mf], bh[nf]);
                mma16816(acc[mf][nf], ah[mf], bl[nf]);
                mma16816(acc[mf][nf], al[mf], bh[nf]);
            }
    }
}
template<int MF>
__device__ __forceinline__ void zero_acc(float (*acc)[4][4]) {
    #pragma unroll
    for (int mf = 0; mf < MF; ++mf)
        #pragma unroll
        for (int nf = 0; nf < 4; ++nf)
            acc[mf][nf][0] = acc[mf][nf][1] = acc[mf][nf][2] = acc[mf][nf][3] = 0.f;
}

// epilogue: relu(acc+b) (+mean[g]) re-split into A tiles
template<int MF, bool ADDMEAN, int SHIFT>
__device__ __forceinline__ void epi_resplit(float (*acc)[4][4],
                                            const float* __restrict__ bias,
                                            const float* __restrict__ meanv,
                                            char* pAh, char* pAl,
                                            int row0, int m0, int n0, int lane)
{
    const int tq = lane & 3, gq = lane >> 2;
    #pragma unroll
    for (int mf = 0; mf < MF; ++mf) {
        const int r0 = m0 + mf * 16 + gq;
        const int g = ADDMEAN ? ((SHIFT == 6) ? ((row0 + m0) >> 6)
                                              : ((row0 + m0 + mf * 16) >> 4)) : 0;
        #pragma unroll
        for (int nf = 0; nf < 4; ++nf) {
            const int c = n0 + nf * 8 + 2 * tq;
            float mx = 0.f, my = 0.f;
            if (ADDMEAN) {
                const float2 mv = *reinterpret_cast<const float2*>(&meanv[g * Hc + c]);
                mx = mv.x; my = mv.y;
            }
            const float bb0 = bias[c], bb1 = bias[c + 1];
            const float e0 = fmaxf(acc[mf][nf][0] + bb0, 0.f) + mx;
            const float e1 = fmaxf(acc[mf][nf][1] + bb1, 0.f) + my;
            const float e2 = fmaxf(acc[mf][nf][2] + bb0, 0.f) + mx;
            const float e3 = fmaxf(acc[mf][nf][3] + bb1, 0.f) + my;
            uint32_t hi0, lo0, hi1, lo1;
            split2(e0, e1, hi0, lo0);
            split2(e2, e3, hi1, lo1);
            *reinterpret_cast<uint32_t*>(pAh + r0 * ASTR + c * 2) = hi0;
            *reinterpret_cast<uint32_t*>(pAl + r0 * ASTR + c * 2) = lo0;
            *reinterpret_cast<uint32_t*>(pAh + (r0 + 8) * ASTR + c * 2) = hi1;
            *reinterpret_cast<uint32_t*>(pAl + (r0 + 8) * ASTR + c * 2) = lo1;
        }
    }
}

// mean-16 epilogue: each 16-row m-frag is one group
template<int MF>
__device__ __forceinline__ void epi_mean16(float (*acc)[4][4],
                                           const float* __restrict__ bias,
                                           float* __restrict__ outp,
                                           int row0, int m0, int n0, int lane)
{
    const int tq = lane & 3;
    #pragma unroll
    for (int mf = 0; mf < MF; ++mf) {
        const int grp = (row0 + m0 + mf * 16) >> 4;
        #pragma unroll
        for (int nf = 0; nf < 4; ++nf) {
            const int c = n0 + nf * 8 + 2 * tq;
            const float bb0 = bias[c], bb1 = bias[c + 1];
            float s0 = fmaxf(acc[mf][nf][0] + bb0, 0.f)
                     + fmaxf(acc[mf][nf][2] + bb0, 0.f);
            float s1 = fmaxf(acc[mf][nf][1] + bb1, 0.f)
                     + fmaxf(acc[mf][nf][3] + bb1, 0.f);
            s0 += __shfl_xor_sync(~0u, s0, 4);  s1 += __shfl_xor_sync(~0u, s1, 4);
            s0 += __shfl_xor_sync(~0u, s0, 8);  s1 += __shfl_xor_sync(~0u, s1, 8);
            s0 += __shfl_xor_sync(~0u, s0, 16); s1 += __shfl_xor_sync(~0u, s1, 16);
            if (lane < 4) {
                float2 o2 = {s0 * 0.0625f, s1 * 0.0625f};
                *reinterpret_cast<float2*>(&outp[grp * Hc + n0 + nf * 8 + 2 * lane]) = o2;
            }
        }
    }
}

// ---------------------------------------------------------------------------
// K1: prep (blocks 0..6) + stage1 (blocks 7..38)   [NTK1=512 threads]
// ---------------------------------------------------------------------------
__global__ __launch_bounds__(NTK1, 1)
void k1_prep_stage1(const float* W0, const float* W1, const float* W2,
                    const float* W3, const float* W4, const float* W5,
                    const float* Wn,
                    __nv_bfloat16* oh, __nv_bfloat16* ol,
                    const float* __restrict__ uf,
                    const float* __restrict__ W_ue, const float* __restrict__ b_ue,
                    const float* __restrict__ W_t,  const float* __restrict__ b_t,
                    float* __restrict__ hu, float* __restrict__ hag)
{
    extern __shared__ char smraw[];
    const int tid = threadIdx.x;

    if (blockIdx.x < 7) {
        float* st = reinterpret_cast<float*>(smraw);
        const int m = blockIdx.x;
        uint32_t* ph = reinterpret_cast<uint32_t*>(oh + (size_t)m * Hc * Hc);
        uint32_t* pl = reinterpret_cast<uint32_t*>(ol + (size_t)m * Hc * Hc);
        if (m < 6) {
            const float* Ws[6] = {W0, W1, W2, W3, W4, W5};
            const float* W = Ws[m];
            for (int i = tid; i < Hc * 32; i += NTK1) {
                const int kr = i >> 5, c4 = i & 31;
                *reinterpret_cast<float4*>(&st[kr * 132 + c4 * 4]) =
                    reinterpret_cast<const float4*>(W)[i];
            }
            __syncthreads();
            for (int i = tid; i < Hc * 64; i += NTK1) {
                const int n = i >> 6, k2 = (i & 63) * 2;
                uint32_t hi, lo;
                split2(st[k2 * 132 + n], st[(k2 + 1) * 132 + n], hi, lo);
                ph[n * 64 + (i & 63)] = hi;
                pl[n * 64 + (i & 63)] = lo;
            }
        } else {
            for (int i = tid; i < Hc * 8; i += NTK1) {
                const int kr = i >> 3, c4 = i & 7;
                *reinterpret_cast<float4*>(&st[kr * 36 + c4 * 4]) =
                    reinterpret_cast<const float4*>(Wn)[i];
            }
            __syncthreads();
            for (int i = tid; i < 64 * 64; i += NTK1) {
                const int rowp = i >> 6, k = (i & 63) * 2;
                uint32_t hi = 0, lo = 0;
                if (rowp < 32) {
                    const int n = (rowp & 1) * 16 + (rowp >> 1);
                    split2(st[k * 36 + n], st[(k + 1) * 36 + n], hi, lo);
                }
                ph[rowp * 64 + (i & 63)] = hi;
                pl[rowp * 64 + (i & 63)] = lo;
            }
        }
        return;
    }

    // ---- stage1 ----
    float* sA    = reinterpret_cast<float*>(smraw);           // [128][36]
    float* sW    = reinterpret_cast<float*>(smraw + 18432);   // [32][128]
    float* spart = reinterpret_cast<float*>(smraw + 65536);   // [16][132]
    float* smean = reinterpret_cast<float*>(smraw + 73984);   // [8][132]
    float* sWt   = reinterpret_cast<float*>(smraw);           // phase2: [128][128]

    const int row0 = (blockIdx.x - 7) * 128;

    for (int i = tid; i < 1024; i += NTK1) {
        const int r = i >> 3, k4 = i & 7;
        *reinterpret_cast<float4*>(&sA[r * 36 + k4 * 4]) =
            reinterpret_cast<const float4*>(uf)[(size_t)row0 * 8 + i];
    }
    for (int i = tid; i < 1024; i += NTK1)
        reinterpret_cast<float4*>(sW)[i] = reinterpret_cast<const float4*>(W_ue)[i];
    __syncthreads();

    {
        const int tx = tid & 31, ty = tid >> 5;
        const float4 b4 = reinterpret_cast<const float4*>(b_ue)[tx];
        float4 msum = {0.f, 0.f, 0.f, 0.f};
        #pragma unroll 2
        for (int i = 0; i < 8; ++i) {
            const int r = ty * 8 + i;
            float4 acc = b4;
            #pragma unroll
            for (int k = 0; k < 32; ++k) {
                const float a = sA[r * 36 + k];
                const float4 w = reinterpret_cast<const float4*>(sW)[k * 32 + tx];
                acc.x += a * w.x; acc.y += a * w.y; acc.z += a * w.z; acc.w += a * w.w;
            }
            acc.x = fmaxf(acc.x, 0.f); acc.y = fmaxf(acc.y, 0.f);
            acc.z = fmaxf(acc.z, 0.f); acc.w = fmaxf(acc.w, 0.f);
            reinterpret_cast<float4*>(hu)[(size_t)(row0 + r) * 32 + tx] = acc;
            msum.x += acc.x; msum.y += acc.y; msum.z += acc.z; msum.w += acc.w;
        }
        *reinterpret_cast<float4*>(&spart[ty * 132 + tx * 4]) = msum;
    }
    __syncthreads();
    for (int i = tid; i < 1024; i += NTK1) {
        const int g = i >> 7, c = i & 127;
        smean[g * 132 + c] = (spart[(2*g) * 132 + c] + spart[(2*g+1) * 132 + c]) * 0.0625f;
    }
    __syncthreads();
    for (int i = tid; i < 4096; i += NTK1)
        reinterpret_cast<float4*>(sWt)[i] = reinterpret_cast<const float4*>(W_t)[i];
    __syncthreads();
    if (tid < 256) {
        const int gr = tid >> 5, col4 = tid & 31;
        float4 acc = reinterpret_cast<const float4*>(b_t)[col4];
        #pragma unroll 4
        for (int k = 0; k < 128; ++k) {
            const float a = smean[gr * 132 + k];
            const float4 w = reinterpret_cast<const float4*>(sWt)[k * 32 + col4];
            acc.x += a * w.x; acc.y += a * w.y; acc.z += a * w.z; acc.w += a * w.w;
        }
        acc.x = fmaxf(acc.x, 0.f); acc.y = fmaxf(acc.y, 0.f);
        acc.z = fmaxf(acc.z, 0.f); acc.w = fmaxf(acc.w, 0.f);
        reinterpret_cast<float4*>(hag)[(size_t)((blockIdx.x - 7) * 8 + gr) * 32 + col4] = acc;
    }
}

// ---------------------------------------------------------------------------
// Single GEMM -> group mean only.
//  OUTMODE 1: group=16 rows.  OUTMODE 2: group=64 rows (TM=128, WM=64).
// ---------------------------------------------------------------------------
template<int TM, int SHIFT, int OUTMODE>
__global__ __launch_bounds__(NT, 1)
void gemm_aggr(const float* __restrict__ A, const float* __restrict__ addv,
               const __nv_bfloat16* __restrict__ Wh, const __nv_bfloat16* __restrict__ Wl,
               const float* __restrict__ bias, float* __restrict__ outp)
{
    extern __shared__ char sm[];
    constexpr int TILEA = TM * ASTR;
    char* pAh = sm;
    char* pAl = sm + TILEA;
    char* pBh = sm + 2 * TILEA;
    char* pBl = pBh + T128;

    const int tid = threadIdx.x;
    const int row0 = blockIdx.x * TM;
    const uint32_t base = smem_u32(sm);

    load_B_async(Wh, Wl, base + 2 * TILEA, base + 2 * TILEA + T128, tid, 128);
    CP_COMMIT();
    load_split_A<TM, SHIFT>(A, addv, row0, pAh, pAl, tid);
    CP_WAIT(0);
    __syncthreads();

    constexpr int WM = TM / 2, MF = WM / 16;
    const int w = tid >> 5, lane = tid & 31;
    const int m0 = (w >> 2) * WM, n0 = (w & 3) * 32;
    const int rr = lane & 7, quad = lane >> 3;
    const uint32_t a_off = (uint32_t)((m0 + rr + ((quad & 1) << 3)) * ASTR + ((quad & 2) << 3));
    const uint32_t b_off = (uint32_t)((n0 + rr + ((quad >> 1) << 3)) * ASTR + ((quad & 1) << 4));

    float acc[MF][4][4];
    zero_acc<MF>(acc);
    mma_merged<MF, 4>(base, base + TILEA, base + 2 * TILEA, base + 2 * TILEA + T128,
                      a_off, b_off, acc);

    if (OUTMODE == 1) {
        epi_mean16<MF>(acc, bias, outp, row0, m0, n0, lane);
    } else {
        // group = 64 rows = full warp-tile M (WM=64)
        const int tq = lane & 3;
        float s0[4], s1[4];
        #pragma unroll
        for (int nf = 0; nf < 4; ++nf) { s0[nf] = 0.f; s1[nf] = 0.f; }
        #pragma unroll
        for (int mf = 0; mf < MF; ++mf)
            #pragma unroll
            for (int nf = 0; nf < 4; ++nf) {
                const int c = n0 + nf * 8 + 2 * tq;
                const float bb0 = bias[c], bb1 = bias[c + 1];
                s0[nf] += fmaxf(acc[mf][nf][0] + bb0, 0.f)
                        + fmaxf(acc[mf][nf][2] + bb0, 0.f);
                s1[nf] += fmaxf(acc[mf][nf][1] + bb1, 0.f)
                        + fmaxf(acc[mf][nf][3] + bb1, 0.f);
            }
        const int grp = (row0 + m0) >> 6;
        #pragma unroll
        for (int nf = 0; nf < 4; ++nf) {
            float a0 = s0[nf], a1 = s1[nf];
            a0 += __shfl_xor_sync(~0u, a0, 4);  a1 += __shfl_xor_sync(~0u, a1, 4);
            a0 += __shfl_xor_sync(~0u, a0, 8);  a1 += __shfl_xor_sync(~0u, a1, 8);
            a0 += __shfl_xor_sync(~0u, a0, 16); a1 += __shfl_xor_sync(~0u, a1, 16);
            if (lane < 4) {
                float2 o2 = {a0 * (1.f/64.f), a1 * (1.f/64.f)};
                *reinterpret_cast<float2*>(&outp[grp * Hc + n0 + nf * 8 + 2 * lane]) = o2;
            }
        }
    }
}

// ---------------------------------------------------------------------------
// Agent dual (TM=128): ha2 = relu((relu((noise+hag)@W1+b1)+meanA[g64])@W2+b2)
// 6-tile smem, B2 prefetched via cp.async during GEMM1.
// ---------------------------------------------------------------------------
__global__ __launch_bounds__(NT, 1)
void gemm_dual_agent(const float* __restrict__ noise, const float* __restrict__ hag,
                     const __nv_bfloat16* W1h, const __nv_bfloat16* W1l,
                     const float* b1, const float* __restrict__ meanv,
                     const __nv_bfloat16* W2h, const __nv_bfloat16* W2l,
                     const float* b2, float* __restrict__ outp)
{
    extern __shared__ char sm[];
    char* pAh = sm;
    char* pAl = sm + T128;
    const uint32_t base = smem_u32(sm);
    const uint32_t b1h = base + 2 * T128, b1l = base + 3 * T128;
    const uint32_t b2h = base + 4 * T128, b2l = base + 5 * T128;

    const int tid = threadIdx.x;
    const int row0 = blockIdx.x * 128;

    load_B_async(W1h, W1l, b1h, b1l, tid, 128);
    CP_COMMIT();                                        // G0
    load_split_A<128, 6>(noise, hag, row0, pAh, pAl, tid);
    load_B_async(W2h, W2l, b2h, b2l, tid, 128);
    CP_COMMIT();                                        // G1
    CP_WAIT(1);                                         // B1 ready
    __syncthreads();

    constexpr int MF = 4;
    const int w = tid >> 5, lane = tid & 31;
    const int m0 = (w >> 2) * 64, n0 = (w & 3) * 32;
    const int rr = lane & 7, quad = lane >> 3;
    const uint32_t a_off = (uint32_t)((m0 + rr + ((quad & 1) << 3)) * ASTR + ((quad & 2) << 3));
    const uint32_t b_off = (uint32_t)((n0 + rr + ((quad >> 1) << 3)) * ASTR + ((quad & 1) << 4));

    float acc[MF][4][4];
    zero_acc<MF>(acc);
    mma_merged<MF, 4>(base, base + T128, b1h, b1l, a_off, b_off, acc);
    __syncthreads();
    epi_resplit<MF, true, 6>(acc, b1, meanv, pAh, pAl, row0, m0, n0, lane);
    CP_WAIT(0);                                         // B2 ready
    __syncthreads();
    zero_acc<MF>(acc);
    mma_merged<MF, 4>(base, base + T128, b2h, b2l, a_off, b_off, acc);

    const int tq = lane & 3, gq = lane >> 2;
    #pragma unroll
    for (int mf = 0; mf < MF; ++mf) {
        const int row = row0 + m0 + mf * 16 + gq;
        #pragma unroll
        for (int nf = 0; nf < 4; ++nf) {
            const int c = n0 + nf * 8 + 2 * tq;
            const float bb0 = b2[c], bb1 = b2[c + 1];
            float2 lo = {fmaxf(acc[mf][nf][0] + bb0, 0.f),
                         fmaxf(acc[mf][nf][1] + bb1, 0.f)};
            float2 hi = {fmaxf(acc[mf][nf][2] + bb0, 0.f),
                         fmaxf(acc[mf][nf][3] + bb1, 0.f)};
            *reinterpret_cast<float2*>(&outp[(size_t)row * Hc + c]) = lo;
            *reinterpret_cast<float2*>(&outp[(size_t)(row + 8) * Hc + c]) = hi;
        }
    }
}

// ---------------------------------------------------------------------------
// User triple (TM=64, grid 64): meanA2 = mean16(relu(
//    relu((relu(hu@W4+b4)+meanU[g16])@W5+b5) @ W0 + b0))
// ---------------------------------------------------------------------------
__global__ __launch_bounds__(NT, 1)
void gemm_user_triple(const float* __restrict__ hu,
                      const __nv_bfloat16* W4h, const __nv_bfloat16* W4l, const float* b4,
                      const float* __restrict__ meanU,
                      const __nv_bfloat16* W5h, const __nv_bfloat16* W5l, const float* b5,
                      const __nv_bfloat16* W0h, const __nv_bfloat16* W0l, const float* b0,
                      float* __restrict__ meanA2)
{
    extern __shared__ char sm[];
    char* pAh = sm;
    char* pAl = sm + T64;
    const uint32_t base = smem_u32(sm);
    const uint32_t b1h = base + 2 * T64,        b1l = base + 2 * T64 + T128;
    const uint32_t b2h = base + 2 * T64 + 2 * T128, b2l = base + 2 * T64 + 3 * T128;

    const int tid = threadIdx.x;
    const int row0 = blockIdx.x * 64;

    load_B_async(W4h, W4l, b1h, b1l, tid, 128);
    CP_COMMIT();                                        // G0
    load_split_A<64, 4>(hu, nullptr, row0, pAh, pAl, tid);
    load_B_async(W5h, W5l, b2h, b2l, tid, 128);
    CP_COMMIT();                                        // G1
    CP_WAIT(1);
    __syncthreads();

    constexpr int MF = 2;
    const int w = tid >> 5, lane = tid & 31;
    const int m0 = (w >> 2) * 32, n0 = (w & 3) * 32;
    const int rr = lane & 7, quad = lane >> 3;
    const uint32_t a_off = (uint32_t)((m0 + rr + ((quad & 1) << 3)) * ASTR + ((quad & 2) << 3));
    const uint32_t b_off = (uint32_t)((n0 + rr + ((quad >> 1) << 3)) * ASTR + ((quad & 1) << 4));

    float acc[MF][4][4];
    zero_acc<MF>(acc);
    mma_merged<MF, 4>(base, base + T64, b1h, b1l, a_off, b_off, acc);
    __syncthreads();
    epi_resplit<MF, true, 4>(acc, b4, meanU, pAh, pAl, row0, m0, n0, lane);
    load_B_async(W0h, W0l, b1h, b1l, tid, 128);         // B3 into B1 slot
    CP_COMMIT();                                        // G2
    CP_WAIT(1);                                         // B2 ready
    __syncthreads();
    zero_acc<MF>(acc);
    mma_merged<MF, 4>(base, base + T64, b2h, b2l, a_off, b_off, acc);
    __syncthreads();
    epi_resplit<MF, false, 0>(acc, b5, nullptr, pAh, pAl, row0, m0, n0, lane);
    CP_WAIT(0);                                         // B3 ready
    __syncthreads();
    zero_acc<MF>(acc);
    mma_merged<MF, 4>(base, base + T64, b1h, b1l, a_off, b_off, acc);
    epi_mean16<MF>(acc, b0, meanA2, row0, m0, n0, lane);
}

// ---------------------------------------------------------------------------
// Final triple (TM=128): out = normalize(
//    relu((relu(ha2@W1+b1)+meanA2[g16-per-row? g64])@W2+b2) @ W_norm' + b_norm )
// ---------------------------------------------------------------------------
__global__ __launch_bounds__(NT, 1)
void gemm_final(const float* __restrict__ ha2,
                const __nv_bfloat16* W1h, const __nv_bfloat16* W1l, const float* b1,
                const float* __restrict__ meanA2,
                const __nv_bfloat16* W2h, const __nv_bfloat16* W2l, const float* b2,
                const __nv_bfloat16* W6h, const __nv_bfloat16* W6l, const float* b_norm,
                float* __restrict__ outp)
{
    extern __shared__ char sm[];
    char* pAh = sm;
    char* pAl = sm + T128;
    const uint32_t base = smem_u32(sm);
    const uint32_t b1h = base + 2 * T128, b1l = base + 3 * T128;
    const uint32_t b2h = base + 4 * T128, b2l = base + 5 * T128;

    const int tid = threadIdx.x;
    const int row0 = blockIdx.x * 128;

    load_B_async(W1h, W1l, b1h, b1l, tid, 128);
    CP_COMMIT();                                        // G0
    load_split_A<128, 6>(ha2, nullptr, row0, pAh, pAl, tid);
    load_B_async(W2h, W2l, b2h, b2l, tid, 128);
    CP_COMMIT();                                        // G1
    CP_WAIT(1);
    __syncthreads();

    constexpr int MF = 4;
    const int w = tid >> 5, lane = tid & 31;
    const int m0 = (w >> 2) * 64, n0 = (w & 3) * 32;
    const int rr = lane & 7, quad = lane >> 3;
    const uint32_t a_off = (uint32_t)((m0 + rr + ((quad & 1) << 3)) * ASTR + ((quad & 2) << 3));
    const uint32_t b_off = (uint32_t)((n0 + rr + ((quad >> 1) << 3)) * ASTR + ((quad & 1) << 4));

    float acc[MF][4][4];
    zero_acc<MF>(acc);
    mma_merged<MF, 4>(base, base + T128, b1h, b1l, a_off, b_off, acc);
    __syncthreads();
    epi_resplit<MF, true, 6>(acc, b1, meanA2, pAh, pAl, row0, m0, n0, lane);
    load_B_async(W6h, W6l, b1h, b1l, tid, 64);          // W_norm' into B1
    CP_COMMIT();                                        // G2
    CP_WAIT(1);                                         // B2 ready
    __syncthreads();
    zero_acc<MF>(acc);
    mma_merged<MF, 4>(base, base + T128, b2h, b2l, a_off, b_off, acc);
    __syncthreads();
    epi_resplit<MF, false, 0>(acc, b2, nullptr, pAh, pAl, row0, m0, n0, lane);
    CP_WAIT(0);                                         // W_norm' ready
    __syncthreads();

    // GEMM3: N=64 padded (cols 0..31 real = interleaved re/im), NF=2 per warp
    const int n03 = (w & 3) * 16;
    const uint32_t b_off3 = (uint32_t)((n03 + rr + ((quad >> 1) << 3)) * ASTR + ((quad & 1) << 4));
    float acc3[MF][2][4];
    #pragma unroll
    for (int mf = 0; mf < MF; ++mf)
        #pragma unroll
        for (int nf = 0; nf < 2; ++nf)
            acc3[mf][nf][0] = acc3[mf][nf][1] = acc3[mf][nf][2] = acc3[mf][nf][3] = 0.f;
    mma_merged<MF, 2>(base, base + T128, b1h, b1l, a_off, b_off3, acc3);

    if ((w & 3) < 2) {
        const int tq = lane & 3, gq = lane >> 2;
        #pragma unroll
        for (int mf = 0; mf < MF; ++mf) {
            const int row = row0 + m0 + mf * 16 + gq;
            #pragma unroll
            for (int nf = 0; nf < 2; ++nf) {
                const int c = n03 + nf * 8 + 2 * tq;   // even; rf = c/2
                const int rf = c >> 1;
                const float br = b_norm[rf], bi = b_norm[rf + NRFc];
                {
                    const float re = acc3[mf][nf][0] + br;
                    const float im = acc3[mf][nf][1] + bi;
                    const float inv = rsqrtf(re * re + im * im);
                    float2 o = {re * inv, im * inv};
                    *reinterpret_cast<float2*>(&outp[(size_t)row * 32 + c]) = o;
                }
                {
                    const float re = acc3[mf][nf][2] + br;
                    const float im = acc3[mf][nf][3] + bi;
                    const float inv = rsqrtf(re * re + im * im);
                    float2 o = {re * inv, im * inv};
                    *reinterpret_cast<float2*>(&outp[(size_t)(row + 8) * 32 + c]) = o;
                }
            }
        }
    }
}

// ---------------------------------------------------------------------------
// Host
// ---------------------------------------------------------------------------
extern "C" void kernel_launch(void* const* d_in, const int* in_sizes, int n_in,
                              void* d_out, int out_size)
{
    (void)in_sizes; (void)n_in; (void)out_size;

    const float* user_feat = (const float*)d_in[0];
    const float* noise     = (const float*)d_in[1];
    const float* W_ue     = (const float*)d_in[6],  *b_ue     = (const float*)d_in[7];
    const float* W_t      = (const float*)d_in[8],  *b_t      = (const float*)d_in[9];
    const float* b_aggr_a = (const float*)d_in[11];
    const float* b_self_a = (const float*)d_in[13];
    const float* b_comb_a = (const float*)d_in[15];
    const float* b_aggr_u = (const float*)d_in[17];
    const float* b_self_u = (const float*)d_in[19];
    const float* b_comb_u = (const float*)d_in[21];
    const float* W_norm   = (const float*)d_in[22], *b_norm   = (const float*)d_in[23];
    float* out = (float*)d_out;

    float *hu, *ha2, *meanA, *meanU, *meanA2, *hag;
    __nv_bfloat16 *wth, *wtl;
    cudaGetSymbolAddress((void**)&hu,     g_hu);
    cudaGetSymbolAddress((void**)&ha2,    g_ha2);
    cudaGetSymbolAddress((void**)&meanA,  g_meanA);
    cudaGetSymbolAddress((void**)&meanU,  g_meanU);
    cudaGetSymbolAddress((void**)&meanA2, g_meanA2);
    cudaGetSymbolAddress((void**)&hag,    g_hag);
    cudaGetSymbolAddress((void**)&wth,    g_wt_hi);
    cudaGetSymbolAddress((void**)&wtl,    g_wt_lo);

    constexpr int SM_K1   = 78208;
    constexpr int SM_AG64  = 2 * T64  + 2 * T128;   // 104448
    constexpr int SM_AG128 = 2 * T128 + 2 * T128;   // 139264
    constexpr int SM_DUAL  = 6 * T128;              // 208896
    constexpr int SM_TRI64 = 2 * T64  + 4 * T128;   // 174080

    cudaFuncSetAttribute((void*)k1_prep_stage1, cudaFuncAttributeMaxDynamicSharedMemorySize, SM_K1);
    cudaFuncSetAttribute((void*)gemm_aggr<64,4,1>,  cudaFuncAttributeMaxDynamicSharedMemorySize, SM_AG64);
    cudaFuncSetAttribute((void*)gemm_aggr<128,6,2>, cudaFuncAttributeMaxDynamicSharedMemorySize, SM_AG128);
    cudaFuncSetAttribute((void*)gemm_dual_agent,    cudaFuncAttributeMaxDynamicSharedMemorySize, SM_DUAL);
    cudaFuncSetAttribute((void*)gemm_user_triple,   cudaFuncAttributeMaxDynamicSharedMemorySize, SM_TRI64);
    cudaFuncSetAttribute((void*)gemm_final,         cudaFuncAttributeMaxDynamicSharedMemorySize, SM_DUAL);

    const __nv_bfloat16 *WH0 = wth + 0*16384, *WL0 = wtl + 0*16384;   // aggr_a
    const __nv_bfloat16 *WH1 = wth + 1*16384, *WL1 = wtl + 1*16384;   // self_a
    const __nv_bfloat16 *WH2 = wth + 2*16384, *WL2 = wtl + 2*16384;   // comb_a
    const __nv_bfloat16 *WH3 = wth + 3*16384, *WL3 = wtl + 3*16384;   // aggr_u
    const __nv_bfloat16 *WH4 = wth + 4*16384, *WL4 = wtl + 4*16384;   // self_u
    const __nv_bfloat16 *WH5 = wth + 5*16384, *WL5 = wtl + 5*16384;   // comb_u
    const __nv_bfloat16 *WH6 = wth + 6*16384, *WL6 = wtl + 6*16384;   // W_norm'

    // L1: weight prep + stage1 (grid 39)
    k1_prep_stage1<<<7 + NUSER/128, NTK1, SM_K1>>>(
        (const float*)d_in[10], (const float*)d_in[12], (const float*)d_in[14],
        (const float*)d_in[16], (const float*)d_in[18], (const float*)d_in[20],
        W_norm, wth, wtl,
        user_feat, W_ue, b_ue, W_t, b_t, hu, hag);

    // L2: meanA = mean16(relu(hu @ W_aggr_a + b))            (grid 64)
    gemm_aggr<64,4,1><<<NUSER/64, NT, SM_AG64>>>(hu, nullptr, WH0, WL0, b_aggr_a, meanA);

    // L3: meanU = mean64(relu((noise+hag) @ W_aggr_u + b))   (grid 128)
    gemm_aggr<128,6,2><<<NAG/128, NT, SM_AG128>>>(noise, hag, WH3, WL3, b_aggr_u, meanU);

    // L4: agent dual -> ha2                                   (grid 128)
    gemm_dual_agent<<<NAG/128, NT, SM_DUAL>>>(noise, hag, WH1, WL1, b_self_a,
                                              meanA, WH2, WL2, b_comb_a, ha2);

    // L5: user triple -> meanA2                               (grid 64)
    gemm_user_triple<<<NUSER/64, NT, SM_TRI64>>>(hu, WH4, WL4, b_self_u, meanU,
                                                 WH5, WL5, b_comb_u,
                                                 WH0, WL0, b_aggr_a, meanA2);

    // L6: final triple + normalize -> out                     (grid 128)
    gemm_final<<<NAG/128, NT, SM_DUAL>>>(ha2, WH1, WL1, b_self_a, meanA2,
                                         WH2, WL2, b_comb_a, WH6, WL6, b_norm, out);
}